// round 7
// baseline (speedup 1.0000x reference)
#include <cuda_runtime.h>
#include <math.h>

#define NN 100000
#define NE 3200000
#define EBLK ((NE + 255) / 256)
#define NBLK ((NN + 255) / 256)

// ---------------- scratch ---------------------------------------------------
__device__ float g_tmp[NN * 8];
__device__ float g_agg[NN * 8];
__device__ int2  g_edge[NE];
__device__ int   g_is64;

// ---------------- f32x2 helpers --------------------------------------------
__device__ __forceinline__ unsigned long long bcast2(float x) {
    unsigned long long r;
    unsigned u = __float_as_uint(x);
    asm("mov.b64 %0, {%1, %1};" : "=l"(r) : "r"(u));
    return r;
}
__device__ __forceinline__ void ffma2(unsigned long long& d,
                                      unsigned long long a, unsigned long long b) {
    asm("fma.rn.f32x2 %0, %1, %2, %0;" : "+l"(d) : "l"(a), "l"(b));
}
__device__ __forceinline__ void unpack2(unsigned long long v, float& lo, float& hi) {
    asm("mov.b64 {%0, %1}, %2;" : "=f"(lo), "=f"(hi) : "l"(v));
}

// ---------------- vector reduction (sm_90+) --------------------------------
__device__ __forceinline__ void red4(float* p, float a, float b, float c, float d) {
    asm volatile("red.global.add.v4.f32 [%0], {%1,%2,%3,%4};"
                 :: "l"(p), "f"(a), "f"(b), "f"(c), "f"(d) : "memory");
}

// ---------------- detect int64 vs int32 edge_index -------------------------
__global__ void detect_kernel(const unsigned int* __restrict__ w) {
    unsigned v = w[threadIdx.x * 2 + 1];
    int any = __syncthreads_or(v != 0u);
    if (threadIdx.x == 0) g_is64 = any ? 0 : 1;
}

// ---------------- zero agg --------------------------------------------------
__global__ void zero_agg() {
    int i = blockIdx.x * blockDim.x + threadIdx.x;   // 0 .. 200000-1, float4 units
    if (i < NN * 2) ((float4*)g_agg)[i] = make_float4(0.f, 0.f, 0.f, 0.f);
}

// ---------------- layer-1: g_tmp = x @ W1 (512 -> 8) -----------------------
// Persistent tiles: 625 blocks x 5 node-tiles of 32 nodes. W1 staged ONCE per
// block as transposed f32-pairs in shared; no barriers in the tile loop.
// 8-lane subwarps per node; packed f32x2 FMA; butterfly reduce.
__global__ void l1_kernel(const float* __restrict__ x, const float* __restrict__ W1) {
    __shared__ __align__(16) unsigned long long sh2[2048];   // [p][k] pairs, 16 KB
    const int tid = threadIdx.x;

    // stage transposed pairs: sh2[p*512+k] = {W1[k][2p], W1[k][2p+1]}
#pragma unroll
    for (int j = tid; j < 2048; j += 256) {
        int p = j >> 9, k = j & 511;
        unsigned lo = __float_as_uint(__ldg(&W1[k * 8 + 2 * p]));
        unsigned hi = __float_as_uint(__ldg(&W1[k * 8 + 2 * p + 1]));
        unsigned long long v;
        asm("mov.b64 %0, {%1, %2};" : "=l"(v) : "r"(lo), "r"(hi));
        sh2[j] = v;
    }
    __syncthreads();

    const int lane = tid & 31;
    const int warp = tid >> 5;
    const int g = lane >> 3;
    const int r = lane & 7;

#pragma unroll 1
    for (int t = 0; t < 5; t++) {
        const int node = (blockIdx.x * 5 + t) * 32 + warp * 4 + g;  // 625*5*32 = NN
        const float* xrow = x + (size_t)node * 512;

        unsigned long long acc[4];
#pragma unroll
        for (int p = 0; p < 4; p++) acc[p] = 0ull;

#pragma unroll 8
        for (int i = 0; i < 16; i++) {
            int kbase = i * 32 + r * 4;
            float4 xv = __ldg((const float4*)(xrow + kbase));
            unsigned long long x0 = bcast2(xv.x), x1 = bcast2(xv.y);
            unsigned long long x2 = bcast2(xv.z), x3 = bcast2(xv.w);
#pragma unroll
            for (int p = 0; p < 4; p++) {
                const ulonglong2* wp = (const ulonglong2*)&sh2[p * 512 + kbase];
                ulonglong2 wA = wp[0];
                ulonglong2 wB = wp[1];
                ffma2(acc[p], x0, wA.x);
                ffma2(acc[p], x1, wA.y);
                ffma2(acc[p], x2, wB.x);
                ffma2(acc[p], x3, wB.y);
            }
        }

        float s[8];
#pragma unroll
        for (int p = 0; p < 4; p++) unpack2(acc[p], s[2 * p], s[2 * p + 1]);
#pragma unroll
        for (int d = 1; d < 8; d <<= 1) {
#pragma unroll
            for (int o = 0; o < 8; o++)
                s[o] += __shfl_xor_sync(0xffffffffu, s[o], d);
        }
        if (r == 0) {
            float4* tp = (float4*)(g_tmp + (size_t)node * 8);
            tp[0] = make_float4(s[0], s[1], s[2], s[3]);
            tp[1] = make_float4(s[4], s[5], s[6], s[7]);
        }
    }
}

// ---------------- edge pass 1: fused convert + scatter ---------------------
// Reads raw edge_index (int64/int32), caches {src,dst} to g_edge for later
// passes, and does the layer-1 weighted scatter-add.
__global__ void edgecv_k(const void* __restrict__ edge_index,
                         const float* __restrict__ w) {
    int e = blockIdx.x * blockDim.x + threadIdx.x;
    if (e >= NE) return;
    int s, d;
    if (g_is64) {
        const long long* p = (const long long*)edge_index;
        s = (int)__ldg(&p[e]); d = (int)__ldg(&p[NE + e]);
    } else {
        const int* p = (const int*)edge_index;
        s = __ldg(&p[e]); d = __ldg(&p[NE + e]);
    }
    g_edge[e] = make_int2(s, d);
    float wt = __ldg(&w[e]);
    const float4* ts = (const float4*)(g_tmp + (size_t)s * 8);
    float* ad = g_agg + (size_t)d * 8;
    float4 a = __ldg(ts);
    float4 b = __ldg(ts + 1);
    red4(ad,     a.x * wt, a.y * wt, a.z * wt, a.w * wt);
    red4(ad + 4, b.x * wt, b.y * wt, b.z * wt, b.w * wt);
}

// ---------------- edge scatter (8-wide): agg[dst] += tmp[src] * w ----------
__global__ void edge_k(const float* __restrict__ w) {
    int e = blockIdx.x * blockDim.x + threadIdx.x;
    if (e >= NE) return;
    int2 sd = __ldg(&g_edge[e]);
    float wt = __ldg(&w[e]);
    const float4* ts = (const float4*)(g_tmp + (size_t)sd.x * 8);
    float* ad = g_agg + (size_t)sd.y * 8;
    float4 a = __ldg(ts);
    float4 b = __ldg(ts + 1);
    red4(ad,     a.x * wt, a.y * wt, a.z * wt, a.w * wt);
    red4(ad + 4, b.x * wt, b.y * wt, b.z * wt, b.w * wt);
}

// ---------------- elementwise: tmp = relu(agg + b), zero agg ---------------
__global__ void trelu(const float* __restrict__ b) {
    int n = blockIdx.x * blockDim.x + threadIdx.x;
    if (n >= NN) return;
    float4* arow = (float4*)(g_agg + (size_t)n * 8);
    float4* trow = (float4*)(g_tmp + (size_t)n * 8);
    float4 v0 = arow[0], v1 = arow[1];
    trow[0] = make_float4(fmaxf(v0.x + __ldg(&b[0]), 0.f),
                          fmaxf(v0.y + __ldg(&b[1]), 0.f),
                          fmaxf(v0.z + __ldg(&b[2]), 0.f),
                          fmaxf(v0.w + __ldg(&b[3]), 0.f));
    trow[1] = make_float4(fmaxf(v1.x + __ldg(&b[4]), 0.f),
                          fmaxf(v1.y + __ldg(&b[5]), 0.f),
                          fmaxf(v1.z + __ldg(&b[6]), 0.f),
                          fmaxf(v1.w + __ldg(&b[7]), 0.f));
    float4 z = make_float4(0.f, 0.f, 0.f, 0.f);
    arow[0] = z; arow[1] = z;
}

// ---------------- fused mid: tmp = relu(agg@W2 + b2) @ W3, zero agg --------
__global__ void tmid(const float* __restrict__ W2, const float* __restrict__ b2,
                     const float* __restrict__ W3) {
    int n = blockIdx.x * blockDim.x + threadIdx.x;
    if (n >= NN) return;
    float4* arow = (float4*)(g_agg + (size_t)n * 8);
    float4 v0 = arow[0], v1 = arow[1];
    float h[8] = {v0.x, v0.y, v0.z, v0.w, v1.x, v1.y, v1.z, v1.w};
    float4 z = make_float4(0.f, 0.f, 0.f, 0.f);
    arow[0] = z; arow[1] = z;

    float m[16];
#pragma unroll
    for (int o = 0; o < 16; o++) m[o] = __ldg(&b2[o]);
#pragma unroll
    for (int j = 0; j < 8; j++) {
        float hj = h[j];
#pragma unroll
        for (int o = 0; o < 16; o++)
            m[o] += hj * __ldg(&W2[j * 16 + o]);
    }
#pragma unroll
    for (int o = 0; o < 16; o++) m[o] = fmaxf(m[o], 0.f);

    float acc[8];
#pragma unroll
    for (int o = 0; o < 8; o++) acc[o] = 0.f;
#pragma unroll
    for (int j = 0; j < 16; j++) {
        float mj = m[j];
#pragma unroll
        for (int o = 0; o < 8; o++)
            acc[o] += mj * __ldg(&W3[j * 8 + o]);
    }
    float4* trow = (float4*)(g_tmp + (size_t)n * 8);
    trow[0] = make_float4(acc[0], acc[1], acc[2], acc[3]);
    trow[1] = make_float4(acc[4], acc[5], acc[6], acc[7]);
}

// ---------------- final: out = log_softmax(agg@W4 + b4) --------------------
__global__ void lsm_kernel(const float* __restrict__ W4, const float* __restrict__ b4,
                           float* __restrict__ out) {
    int n = blockIdx.x * blockDim.x + threadIdx.x;
    if (n >= NN) return;
    const float4* arow = (const float4*)(g_agg + (size_t)n * 8);
    float4 v0 = __ldg(arow), v1 = __ldg(arow + 1);
    float h[8] = {v0.x, v0.y, v0.z, v0.w, v1.x, v1.y, v1.z, v1.w};

    float v[10];
#pragma unroll
    for (int o = 0; o < 10; o++) v[o] = __ldg(&b4[o]);
#pragma unroll
    for (int j = 0; j < 8; j++) {
        float hj = h[j];
#pragma unroll
        for (int o = 0; o < 10; o++)
            v[o] += hj * __ldg(&W4[j * 10 + o]);
    }
    float m = -1e30f;
#pragma unroll
    for (int o = 0; o < 10; o++) m = fmaxf(m, v[o]);
    float s = 0.f;
#pragma unroll
    for (int o = 0; o < 10; o++) s += expf(v[o] - m);
    float l = logf(s);
#pragma unroll
    for (int o = 0; o < 10; o++) out[(size_t)n * 10 + o] = v[o] - m - l;
}

// ---------------- launch ---------------------------------------------------
extern "C" void kernel_launch(void* const* d_in, const int* in_sizes, int n_in,
                              void* d_out, int out_size) {
    const float* x  = (const float*)d_in[0];
    const void*  ei = d_in[1];
    const float* ew = (const float*)d_in[2];
    const float* W1 = (const float*)d_in[3];
    const float* b1 = (const float*)d_in[4];
    const float* W2 = (const float*)d_in[5];
    const float* b2 = (const float*)d_in[6];
    const float* W3 = (const float*)d_in[7];
    const float* b3 = (const float*)d_in[8];
    const float* W4 = (const float*)d_in[9];
    const float* b4 = (const float*)d_in[10];
    float* out = (float*)d_out;

    detect_kernel<<<1, 256>>>((const unsigned int*)ei);      // 0
    zero_agg<<<(NN * 2 + 255) / 256, 256>>>();               // 1
    l1_kernel<<<625, 256>>>(x, W1);                          // 2: tmp = x@W1
    edgecv_k<<<EBLK, 256>>>(ei, ew);                         // 3: agg1 = A@tmp (+cache edges)

    trelu<<<NBLK, 256>>>(b1);                                // tmp = relu(agg1+b1), agg=0
    edge_k<<<EBLK, 256>>>(ew);                               // agg2 = A@tmp

    tmid<<<NBLK, 256>>>(W2, b2, W3);                         // tmp = relu(agg2 W2+b2) W3, agg=0
    edge_k<<<EBLK, 256>>>(ew);                               // agg3 = A@tmp

    trelu<<<NBLK, 256>>>(b3);                                // tmp = relu(agg3+b3), agg=0
    edge_k<<<EBLK, 256>>>(ew);                               // agg4 = A@tmp

    lsm_kernel<<<NBLK, 256>>>(W4, b4, out);
}

// round 9
// speedup vs baseline: 1.2039x; 1.2039x over previous
#include <cuda_runtime.h>
#include <math.h>

#define NN 100000
#define NE 3200000
#define EBLK ((NE + 255) / 256)
#define NBLK ((NN + 255) / 256)

// ---------------- scratch ---------------------------------------------------
__device__ float g_tmp[NN * 8];
__device__ float g_agg[NN * 8];
__device__ int2  g_edge[NE];
__device__ int   g_is64;

// ---------------- f32x2 helpers --------------------------------------------
__device__ __forceinline__ unsigned long long bcast2(float x) {
    unsigned long long r;
    unsigned u = __float_as_uint(x);
    asm("mov.b64 %0, {%1, %1};" : "=l"(r) : "r"(u));
    return r;
}
__device__ __forceinline__ void ffma2(unsigned long long& d,
                                      unsigned long long a, unsigned long long b) {
    asm("fma.rn.f32x2 %0, %1, %2, %0;" : "+l"(d) : "l"(a), "l"(b));
}
__device__ __forceinline__ void unpack2(unsigned long long v, float& lo, float& hi) {
    asm("mov.b64 {%0, %1}, %2;" : "=f"(lo), "=f"(hi) : "l"(v));
}

// ---------------- 128-bit vector reduction (sm_90+) ------------------------
__device__ __forceinline__ void red4(float* p, float a, float b, float c, float d) {
    asm volatile("red.global.add.v4.f32 [%0], {%1,%2,%3,%4};"
                 :: "l"(p), "f"(a), "f"(b), "f"(c), "f"(d) : "memory");
}

// ---------------- detect int64 vs int32 edge_index -------------------------
__global__ void detect_kernel(const unsigned int* __restrict__ w) {
    unsigned v = w[threadIdx.x * 2 + 1];
    int any = __syncthreads_or(v != 0u);
    if (threadIdx.x == 0) g_is64 = any ? 0 : 1;
}

// ---------------- zero agg (split into two launches for profile indexing) --
__global__ void zero_agg(int base) {
    int i = base + blockIdx.x * blockDim.x + threadIdx.x;
    if (i < NN * 2) ((float4*)g_agg)[i] = make_float4(0.f, 0.f, 0.f, 0.f);
}

// ---------------- layer-1: g_tmp = x @ W1 (512 -> 8) -----------------------
// 3125 blocks x 32 nodes. 8-lane subwarps per node; W1 in shared as transposed
// f32-pairs with XOR-granule swizzle (conflict-free LDS.128); f32x2 FMA.
// Shared layout: byte addr = i*1024 + r*128 + (((p*2+which) ^ r) * 16)
//   holds pairs {W1[k][2p],W1[k][2p+1]} for k = i*32 + r*4 + which*2 (+1).
__global__ void l1_kernel(const float* __restrict__ x, const float* __restrict__ W1) {
    __shared__ __align__(16) unsigned long long sh2[2048];   // 16 KB
    const int tid = threadIdx.x;

    // stage: 1024 ulonglong2 slots, 4 per thread
#pragma unroll
    for (int s = tid; s < 1024; s += 256) {
        int i  = s >> 6;            // k-chunk
        int r  = (s >> 3) & 7;      // sublane
        int gp = s & 7;             // swizzled granule
        int pw = gp ^ r;            // p*2 + which
        int p = pw >> 1, which = pw & 1;
        int k0 = i * 32 + r * 4 + which * 2;
        unsigned a0 = __float_as_uint(__ldg(&W1[k0 * 8 + 2 * p]));
        unsigned a1 = __float_as_uint(__ldg(&W1[k0 * 8 + 2 * p + 1]));
        unsigned b0 = __float_as_uint(__ldg(&W1[(k0 + 1) * 8 + 2 * p]));
        unsigned b1 = __float_as_uint(__ldg(&W1[(k0 + 1) * 8 + 2 * p + 1]));
        unsigned long long lo, hi;
        asm("mov.b64 %0, {%1, %2};" : "=l"(lo) : "r"(a0), "r"(a1));
        asm("mov.b64 %0, {%1, %2};" : "=l"(hi) : "r"(b0), "r"(b1));
        ulonglong2* dst = (ulonglong2*)((char*)sh2 + s * 16);
        *dst = make_ulonglong2(lo, hi);
    }
    __syncthreads();

    const int lane = tid & 31;
    const int warp = tid >> 5;
    const int g = lane >> 3;
    const int r = lane & 7;
    const int node = blockIdx.x * 32 + warp * 4 + g;   // 3125*32 = NN

    const float* xrow = x + (size_t)node * 512;
    const char* shb = (const char*)sh2 + r * 128;

    unsigned long long acc[4];
#pragma unroll
    for (int p = 0; p < 4; p++) acc[p] = 0ull;

#pragma unroll 8
    for (int i = 0; i < 16; i++) {
        int kbase = i * 32 + r * 4;
        float4 xv = __ldg((const float4*)(xrow + kbase));
        unsigned long long x0 = bcast2(xv.x), x1 = bcast2(xv.y);
        unsigned long long x2 = bcast2(xv.z), x3 = bcast2(xv.w);
        const char* row = shb + i * 1024;
#pragma unroll
        for (int p = 0; p < 4; p++) {
            ulonglong2 wA = *(const ulonglong2*)(row + (((p * 2 + 0) ^ r) << 4));
            ulonglong2 wB = *(const ulonglong2*)(row + (((p * 2 + 1) ^ r) << 4));
            ffma2(acc[p], x0, wA.x);
            ffma2(acc[p], x1, wA.y);
            ffma2(acc[p], x2, wB.x);
            ffma2(acc[p], x3, wB.y);
        }
    }

    float s[8];
#pragma unroll
    for (int p = 0; p < 4; p++) unpack2(acc[p], s[2 * p], s[2 * p + 1]);
#pragma unroll
    for (int d = 1; d < 8; d <<= 1) {
#pragma unroll
        for (int o = 0; o < 8; o++)
            s[o] += __shfl_xor_sync(0xffffffffu, s[o], d);
    }
    if (r == 0) {
        float4* tp = (float4*)(g_tmp + (size_t)node * 8);
        tp[0] = make_float4(s[0], s[1], s[2], s[3]);
        tp[1] = make_float4(s[4], s[5], s[6], s[7]);
    }
}

// ---------------- edge pass 1: fused convert + scatter ---------------------
__global__ void edgecv_k(const void* __restrict__ edge_index,
                         const float* __restrict__ w) {
    int e = blockIdx.x * blockDim.x + threadIdx.x;
    if (e >= NE) return;
    int s, d;
    if (g_is64) {
        const long long* p = (const long long*)edge_index;
        s = (int)__ldg(&p[e]); d = (int)__ldg(&p[NE + e]);
    } else {
        const int* p = (const int*)edge_index;
        s = __ldg(&p[e]); d = __ldg(&p[NE + e]);
    }
    g_edge[e] = make_int2(s, d);
    float wt = __ldg(&w[e]);
    const float4* ts = (const float4*)(g_tmp + (size_t)s * 8);
    float* ad = g_agg + (size_t)d * 8;
    float4 a = __ldg(ts);
    float4 b = __ldg(ts + 1);
    red4(ad,     a.x * wt, a.y * wt, a.z * wt, a.w * wt);
    red4(ad + 4, b.x * wt, b.y * wt, b.z * wt, b.w * wt);
}

// ---------------- edge scatter: agg[dst] += tmp[src] * w -------------------
__global__ void edge_k(const float* __restrict__ w) {
    int e = blockIdx.x * blockDim.x + threadIdx.x;
    if (e >= NE) return;
    int2 sd = __ldg(&g_edge[e]);
    float wt = __ldg(&w[e]);
    const float4* ts = (const float4*)(g_tmp + (size_t)sd.x * 8);
    float* ad = g_agg + (size_t)sd.y * 8;
    float4 a = __ldg(ts);
    float4 b = __ldg(ts + 1);
    red4(ad,     a.x * wt, a.y * wt, a.z * wt, a.w * wt);
    red4(ad + 4, b.x * wt, b.y * wt, b.z * wt, b.w * wt);
}

// ---------------- elementwise: tmp = relu(agg + b), zero agg ---------------
__global__ void trelu(const float* __restrict__ b) {
    int n = blockIdx.x * blockDim.x + threadIdx.x;
    if (n >= NN) return;
    float4* arow = (float4*)(g_agg + (size_t)n * 8);
    float4* trow = (float4*)(g_tmp + (size_t)n * 8);
    float4 v0 = arow[0], v1 = arow[1];
    trow[0] = make_float4(fmaxf(v0.x + __ldg(&b[0]), 0.f),
                          fmaxf(v0.y + __ldg(&b[1]), 0.f),
                          fmaxf(v0.z + __ldg(&b[2]), 0.f),
                          fmaxf(v0.w + __ldg(&b[3]), 0.f));
    trow[1] = make_float4(fmaxf(v1.x + __ldg(&b[4]), 0.f),
                          fmaxf(v1.y + __ldg(&b[5]), 0.f),
                          fmaxf(v1.z + __ldg(&b[6]), 0.f),
                          fmaxf(v1.w + __ldg(&b[7]), 0.f));
    float4 z = make_float4(0.f, 0.f, 0.f, 0.f);
    arow[0] = z; arow[1] = z;
}

// ---------------- fused mid: tmp = relu(agg@W2 + b2) @ W3, zero agg --------
__global__ void tmid(const float* __restrict__ W2, const float* __restrict__ b2,
                     const float* __restrict__ W3) {
    int n = blockIdx.x * blockDim.x + threadIdx.x;
    if (n >= NN) return;
    float4* arow = (float4*)(g_agg + (size_t)n * 8);
    float4 v0 = arow[0], v1 = arow[1];
    float h[8] = {v0.x, v0.y, v0.z, v0.w, v1.x, v1.y, v1.z, v1.w};
    float4 z = make_float4(0.f, 0.f, 0.f, 0.f);
    arow[0] = z; arow[1] = z;

    float m[16];
#pragma unroll
    for (int o = 0; o < 16; o++) m[o] = __ldg(&b2[o]);
#pragma unroll
    for (int j = 0; j < 8; j++) {
        float hj = h[j];
#pragma unroll
        for (int o = 0; o < 16; o++)
            m[o] += hj * __ldg(&W2[j * 16 + o]);
    }
#pragma unroll
    for (int o = 0; o < 16; o++) m[o] = fmaxf(m[o], 0.f);

    float acc[8];
#pragma unroll
    for (int o = 0; o < 8; o++) acc[o] = 0.f;
#pragma unroll
    for (int j = 0; j < 16; j++) {
        float mj = m[j];
#pragma unroll
        for (int o = 0; o < 8; o++)
            acc[o] += mj * __ldg(&W3[j * 8 + o]);
    }
    float4* trow = (float4*)(g_tmp + (size_t)n * 8);
    trow[0] = make_float4(acc[0], acc[1], acc[2], acc[3]);
    trow[1] = make_float4(acc[4], acc[5], acc[6], acc[7]);
}

// ---------------- final: out = log_softmax(agg@W4 + b4) --------------------
__global__ void lsm_kernel(const float* __restrict__ W4, const float* __restrict__ b4,
                           float* __restrict__ out) {
    int n = blockIdx.x * blockDim.x + threadIdx.x;
    if (n >= NN) return;
    const float4* arow = (const float4*)(g_agg + (size_t)n * 8);
    float4 v0 = __ldg(arow), v1 = __ldg(arow + 1);
    float h[8] = {v0.x, v0.y, v0.z, v0.w, v1.x, v1.y, v1.z, v1.w};

    float v[10];
#pragma unroll
    for (int o = 0; o < 10; o++) v[o] = __ldg(&b4[o]);
#pragma unroll
    for (int j = 0; j < 8; j++) {
        float hj = h[j];
#pragma unroll
        for (int o = 0; o < 10; o++)
            v[o] += hj * __ldg(&W4[j * 10 + o]);
    }
    float m = -1e30f;
#pragma unroll
    for (int o = 0; o < 10; o++) m = fmaxf(m, v[o]);
    float s = 0.f;
#pragma unroll
    for (int o = 0; o < 10; o++) s += expf(v[o] - m);
    float l = logf(s);
#pragma unroll
    for (int o = 0; o < 10; o++) out[(size_t)n * 10 + o] = v[o] - m - l;
}

// ---------------- launch ---------------------------------------------------
extern "C" void kernel_launch(void* const* d_in, const int* in_sizes, int n_in,
                              void* d_out, int out_size) {
    const float* x  = (const float*)d_in[0];
    const void*  ei = d_in[1];
    const float* ew = (const float*)d_in[2];
    const float* W1 = (const float*)d_in[3];
    const float* b1 = (const float*)d_in[4];
    const float* W2 = (const float*)d_in[5];
    const float* b2 = (const float*)d_in[6];
    const float* W3 = (const float*)d_in[7];
    const float* b3 = (const float*)d_in[8];
    const float* W4 = (const float*)d_in[9];
    const float* b4 = (const float*)d_in[10];
    float* out = (float*)d_out;

    const int HALF = NN;           // NN*2 float4 total, split in two
    detect_kernel<<<1, 256>>>((const unsigned int*)ei);      // 0
    zero_agg<<<(HALF + 255) / 256, 256>>>(0);                // 1
    zero_agg<<<(HALF + 255) / 256, 256>>>(HALF);             // 2
    l1_kernel<<<NN / 32, 256>>>(x, W1);                      // 3 (profiled)
    edgecv_k<<<EBLK, 256>>>(ei, ew);                         // 4: agg1 = A@tmp

    trelu<<<NBLK, 256>>>(b1);
    edge_k<<<EBLK, 256>>>(ew);                               // agg2

    tmid<<<NBLK, 256>>>(W2, b2, W3);
    edge_k<<<EBLK, 256>>>(ew);                               // agg3

    trelu<<<NBLK, 256>>>(b3);
    edge_k<<<EBLK, 256>>>(ew);                               // agg4

    lsm_kernel<<<NBLK, 256>>>(W4, b4, out);
}

// round 10
// speedup vs baseline: 1.2445x; 1.0338x over previous
#include <cuda_runtime.h>
#include <math.h>

#define NN 100000
#define NE 3200000
#define EBLK ((NE + 255) / 256)
#define NBLK ((NN + 255) / 256)

// ---------------- scratch ---------------------------------------------------
__device__ float g_tmp[NN * 8];
__device__ float g_agg[NN * 8];
__device__ int2  g_edge[NE];
__device__ int   g_is64;

// ---------------- f32x2 helpers --------------------------------------------
__device__ __forceinline__ unsigned long long bcast2(float x) {
    unsigned long long r;
    unsigned u = __float_as_uint(x);
    asm("mov.b64 %0, {%1, %1};" : "=l"(r) : "r"(u));
    return r;
}
__device__ __forceinline__ void ffma2(unsigned long long& d,
                                      unsigned long long a, unsigned long long b) {
    asm("fma.rn.f32x2 %0, %1, %2, %0;" : "+l"(d) : "l"(a), "l"(b));
}
__device__ __forceinline__ void unpack2(unsigned long long v, float& lo, float& hi) {
    asm("mov.b64 {%0, %1}, %2;" : "=f"(lo), "=f"(hi) : "l"(v));
}

// ---------------- 128-bit vector reduction (sm_90+) ------------------------
__device__ __forceinline__ void red4(float* p, float a, float b, float c, float d) {
    asm volatile("red.global.add.v4.f32 [%0], {%1,%2,%3,%4};"
                 :: "l"(p), "f"(a), "f"(b), "f"(c), "f"(d) : "memory");
}

// ---------------- detect int64 vs int32 edge_index -------------------------
__global__ void detect_kernel(const unsigned int* __restrict__ w) {
    unsigned v = w[threadIdx.x * 2 + 1];
    int any = __syncthreads_or(v != 0u);
    if (threadIdx.x == 0) g_is64 = any ? 0 : 1;
}

// ---------------- zero agg (split for profile indexing) --------------------
__global__ void zero_agg(int base) {
    int i = base + blockIdx.x * blockDim.x + threadIdx.x;
    if (i < NN * 2) ((float4*)g_agg)[i] = make_float4(0.f, 0.f, 0.f, 0.f);
}

// ---------------- layer-1: g_tmp = x @ W1 (512 -> 8) -----------------------
// 8-lane groups, 4 NODES PER GROUP (W regs reused 4x => LDS traffic 4KB/node).
// 128 nodes/block. W1 in shared as transposed f32-pairs, XOR-granule swizzle.
__global__ void __launch_bounds__(256) l1_kernel(const float* __restrict__ x,
                                                 const float* __restrict__ W1) {
    __shared__ __align__(16) unsigned long long sh2[2048];   // 16 KB
    const int tid = threadIdx.x;

    // stage: slot s -> pairs {W1[k][2p],W1[k][2p+1]}, k = i*32+r*4+which*2
    // byte addr = i*1024 + r*128 + ((p*2+which) ^ r)*16
#pragma unroll
    for (int s = tid; s < 1024; s += 256) {
        int i  = s >> 6;
        int r  = (s >> 3) & 7;
        int gp = s & 7;
        int pw = gp ^ r;
        int p = pw >> 1, which = pw & 1;
        int k0 = i * 32 + r * 4 + which * 2;
        unsigned a0 = __float_as_uint(__ldg(&W1[k0 * 8 + 2 * p]));
        unsigned a1 = __float_as_uint(__ldg(&W1[k0 * 8 + 2 * p + 1]));
        unsigned b0 = __float_as_uint(__ldg(&W1[(k0 + 1) * 8 + 2 * p]));
        unsigned b1 = __float_as_uint(__ldg(&W1[(k0 + 1) * 8 + 2 * p + 1]));
        unsigned long long lo, hi;
        asm("mov.b64 %0, {%1, %2};" : "=l"(lo) : "r"(a0), "r"(a1));
        asm("mov.b64 %0, {%1, %2};" : "=l"(hi) : "r"(b0), "r"(b1));
        *(ulonglong2*)((char*)sh2 + s * 16) = make_ulonglong2(lo, hi);
    }
    __syncthreads();

    const int lane = tid & 31;
    const int warp = tid >> 5;
    const int g = lane >> 3;       // group in warp (0..3)
    const int r = lane & 7;        // sublane

    // 4 nodes per group: 16 nodes/warp, 128 nodes/block
    const int nbase = blockIdx.x * 128 + warp * 16 + g * 4;
    const float* xr0 = x + (size_t)min(nbase + 0, NN - 1) * 512;
    const float* xr1 = x + (size_t)min(nbase + 1, NN - 1) * 512;
    const float* xr2 = x + (size_t)min(nbase + 2, NN - 1) * 512;
    const float* xr3 = x + (size_t)min(nbase + 3, NN - 1) * 512;

    const char* shb = (const char*)sh2 + r * 128;

    unsigned long long acc[4][4];   // [node][p]
#pragma unroll
    for (int j = 0; j < 4; j++)
#pragma unroll
        for (int p = 0; p < 4; p++) acc[j][p] = 0ull;

#pragma unroll 2
    for (int i = 0; i < 16; i++) {
        int kbase = i * 32 + r * 4;
        float4 v0 = __ldg((const float4*)(xr0 + kbase));
        float4 v1 = __ldg((const float4*)(xr1 + kbase));
        float4 v2 = __ldg((const float4*)(xr2 + kbase));
        float4 v3 = __ldg((const float4*)(xr3 + kbase));
        unsigned long long xb[4][4];
        xb[0][0] = bcast2(v0.x); xb[0][1] = bcast2(v0.y); xb[0][2] = bcast2(v0.z); xb[0][3] = bcast2(v0.w);
        xb[1][0] = bcast2(v1.x); xb[1][1] = bcast2(v1.y); xb[1][2] = bcast2(v1.z); xb[1][3] = bcast2(v1.w);
        xb[2][0] = bcast2(v2.x); xb[2][1] = bcast2(v2.y); xb[2][2] = bcast2(v2.z); xb[2][3] = bcast2(v2.w);
        xb[3][0] = bcast2(v3.x); xb[3][1] = bcast2(v3.y); xb[3][2] = bcast2(v3.z); xb[3][3] = bcast2(v3.w);

        const char* row = shb + i * 1024;
#pragma unroll
        for (int p = 0; p < 4; p++) {
            ulonglong2 wA = *(const ulonglong2*)(row + (((p * 2 + 0) ^ r) << 4)); // k+0,k+1
            ulonglong2 wB = *(const ulonglong2*)(row + (((p * 2 + 1) ^ r) << 4)); // k+2,k+3
#pragma unroll
            for (int j = 0; j < 4; j++) {
                ffma2(acc[j][p], xb[j][0], wA.x);
                ffma2(acc[j][p], xb[j][1], wA.y);
                ffma2(acc[j][p], xb[j][2], wB.x);
                ffma2(acc[j][p], xb[j][3], wB.y);
            }
        }
    }

    // per-node 8-lane butterfly reduce + write
#pragma unroll
    for (int j = 0; j < 4; j++) {
        float s[8];
#pragma unroll
        for (int p = 0; p < 4; p++) unpack2(acc[j][p], s[2 * p], s[2 * p + 1]);
#pragma unroll
        for (int d = 1; d < 8; d <<= 1) {
#pragma unroll
            for (int o = 0; o < 8; o++)
                s[o] += __shfl_xor_sync(0xffffffffu, s[o], d);
        }
        int node = nbase + j;
        if (r == 0 && node < NN) {
            float4* tp = (float4*)(g_tmp + (size_t)node * 8);
            tp[0] = make_float4(s[0], s[1], s[2], s[3]);
            tp[1] = make_float4(s[4], s[5], s[6], s[7]);
        }
    }
}

// ---------------- edge pass 1: fused convert + scatter ---------------------
__global__ void edgecv_k(const void* __restrict__ edge_index,
                         const float* __restrict__ w) {
    int e = blockIdx.x * blockDim.x + threadIdx.x;
    if (e >= NE) return;
    int s, d;
    if (g_is64) {
        const long long* p = (const long long*)edge_index;
        s = (int)__ldg(&p[e]); d = (int)__ldg(&p[NE + e]);
    } else {
        const int* p = (const int*)edge_index;
        s = __ldg(&p[e]); d = __ldg(&p[NE + e]);
    }
    g_edge[e] = make_int2(s, d);
    float wt = __ldg(&w[e]);
    const float4* ts = (const float4*)(g_tmp + (size_t)s * 8);
    float* ad = g_agg + (size_t)d * 8;
    float4 a = __ldg(ts);
    float4 b = __ldg(ts + 1);
    red4(ad,     a.x * wt, a.y * wt, a.z * wt, a.w * wt);
    red4(ad + 4, b.x * wt, b.y * wt, b.z * wt, b.w * wt);
}

// ---------------- edge scatter: agg[dst] += tmp[src] * w -------------------
__global__ void edge_k(const float* __restrict__ w) {
    int e = blockIdx.x * blockDim.x + threadIdx.x;
    if (e >= NE) return;
    int2 sd = __ldg(&g_edge[e]);
    float wt = __ldg(&w[e]);
    const float4* ts = (const float4*)(g_tmp + (size_t)sd.x * 8);
    float* ad = g_agg + (size_t)sd.y * 8;
    float4 a = __ldg(ts);
    float4 b = __ldg(ts + 1);
    red4(ad,     a.x * wt, a.y * wt, a.z * wt, a.w * wt);
    red4(ad + 4, b.x * wt, b.y * wt, b.z * wt, b.w * wt);
}

// ---------------- elementwise: tmp = relu(agg + b), zero agg ---------------
__global__ void trelu(const float* __restrict__ b) {
    int n = blockIdx.x * blockDim.x + threadIdx.x;
    if (n >= NN) return;
    float4* arow = (float4*)(g_agg + (size_t)n * 8);
    float4* trow = (float4*)(g_tmp + (size_t)n * 8);
    float4 v0 = arow[0], v1 = arow[1];
    trow[0] = make_float4(fmaxf(v0.x + __ldg(&b[0]), 0.f),
                          fmaxf(v0.y + __ldg(&b[1]), 0.f),
                          fmaxf(v0.z + __ldg(&b[2]), 0.f),
                          fmaxf(v0.w + __ldg(&b[3]), 0.f));
    trow[1] = make_float4(fmaxf(v1.x + __ldg(&b[4]), 0.f),
                          fmaxf(v1.y + __ldg(&b[5]), 0.f),
                          fmaxf(v1.z + __ldg(&b[6]), 0.f),
                          fmaxf(v1.w + __ldg(&b[7]), 0.f));
    float4 z = make_float4(0.f, 0.f, 0.f, 0.f);
    arow[0] = z; arow[1] = z;
}

// ---------------- fused mid: tmp = relu(agg@W2 + b2) @ W3, zero agg --------
__global__ void tmid(const float* __restrict__ W2, const float* __restrict__ b2,
                     const float* __restrict__ W3) {
    int n = blockIdx.x * blockDim.x + threadIdx.x;
    if (n >= NN) return;
    float4* arow = (float4*)(g_agg + (size_t)n * 8);
    float4 v0 = arow[0], v1 = arow[1];
    float h[8] = {v0.x, v0.y, v0.z, v0.w, v1.x, v1.y, v1.z, v1.w};
    float4 z = make_float4(0.f, 0.f, 0.f, 0.f);
    arow[0] = z; arow[1] = z;

    float m[16];
#pragma unroll
    for (int o = 0; o < 16; o++) m[o] = __ldg(&b2[o]);
#pragma unroll
    for (int j = 0; j < 8; j++) {
        float hj = h[j];
#pragma unroll
        for (int o = 0; o < 16; o++)
            m[o] += hj * __ldg(&W2[j * 16 + o]);
    }
#pragma unroll
    for (int o = 0; o < 16; o++) m[o] = fmaxf(m[o], 0.f);

    float acc[8];
#pragma unroll
    for (int o = 0; o < 8; o++) acc[o] = 0.f;
#pragma unroll
    for (int j = 0; j < 16; j++) {
        float mj = m[j];
#pragma unroll
        for (int o = 0; o < 8; o++)
            acc[o] += mj * __ldg(&W3[j * 8 + o]);
    }
    float4* trow = (float4*)(g_tmp + (size_t)n * 8);
    trow[0] = make_float4(acc[0], acc[1], acc[2], acc[3]);
    trow[1] = make_float4(acc[4], acc[5], acc[6], acc[7]);
}

// ---------------- final: out = log_softmax(agg@W4 + b4) --------------------
__global__ void lsm_kernel(const float* __restrict__ W4, const float* __restrict__ b4,
                           float* __restrict__ out) {
    int n = blockIdx.x * blockDim.x + threadIdx.x;
    if (n >= NN) return;
    const float4* arow = (const float4*)(g_agg + (size_t)n * 8);
    float4 v0 = __ldg(arow), v1 = __ldg(arow + 1);
    float h[8] = {v0.x, v0.y, v0.z, v0.w, v1.x, v1.y, v1.z, v1.w};

    float v[10];
#pragma unroll
    for (int o = 0; o < 10; o++) v[o] = __ldg(&b4[o]);
#pragma unroll
    for (int j = 0; j < 8; j++) {
        float hj = h[j];
#pragma unroll
        for (int o = 0; o < 10; o++)
            v[o] += hj * __ldg(&W4[j * 10 + o]);
    }
    float m = -1e30f;
#pragma unroll
    for (int o = 0; o < 10; o++) m = fmaxf(m, v[o]);
    float s = 0.f;
#pragma unroll
    for (int o = 0; o < 10; o++) s += expf(v[o] - m);
    float l = logf(s);
#pragma unroll
    for (int o = 0; o < 10; o++) out[(size_t)n * 10 + o] = v[o] - m - l;
}

// ---------------- launch ---------------------------------------------------
extern "C" void kernel_launch(void* const* d_in, const int* in_sizes, int n_in,
                              void* d_out, int out_size) {
    const float* x  = (const float*)d_in[0];
    const void*  ei = d_in[1];
    const float* ew = (const float*)d_in[2];
    const float* W1 = (const float*)d_in[3];
    const float* b1 = (const float*)d_in[4];
    const float* W2 = (const float*)d_in[5];
    const float* b2 = (const float*)d_in[6];
    const float* W3 = (const float*)d_in[7];
    const float* b3 = (const float*)d_in[8];
    const float* W4 = (const float*)d_in[9];
    const float* b4 = (const float*)d_in[10];
    float* out = (float*)d_out;

    const int HALF = NN;
    detect_kernel<<<1, 256>>>((const unsigned int*)ei);      // 0
    zero_agg<<<(HALF + 255) / 256, 256>>>(0);                // 1
    zero_agg<<<(HALF + 255) / 256, 256>>>(HALF);             // 2
    l1_kernel<<<(NN + 127) / 128, 256>>>(x, W1);             // 3 (profiled)
    edgecv_k<<<EBLK, 256>>>(ei, ew);                         // 4: agg1

    trelu<<<NBLK, 256>>>(b1);
    edge_k<<<EBLK, 256>>>(ew);                               // agg2

    tmid<<<NBLK, 256>>>(W2, b2, W3);
    edge_k<<<EBLK, 256>>>(ew);                               // agg3

    trelu<<<NBLK, 256>>>(b3);
    edge_k<<<EBLK, 256>>>(ew);                               // agg4

    lsm_kernel<<<NBLK, 256>>>(W4, b4, out);
}

// round 11
// speedup vs baseline: 1.2667x; 1.0178x over previous
#include <cuda_runtime.h>
#include <math.h>

#define NN 100000
#define NE 3200000
#define EBLK ((NE + 255) / 256)
#define NBLK ((NN + 255) / 256)

// ---------------- scratch ---------------------------------------------------
__device__ float g_tmp[NN * 8];
__device__ float g_aggA[NN * 8];
__device__ float g_aggB[NN * 8];
__device__ int2  g_edge[NE];
__device__ int   g_is64;

// ---------------- f32x2 helpers --------------------------------------------
__device__ __forceinline__ unsigned long long bcast2(float x) {
    unsigned long long r;
    unsigned u = __float_as_uint(x);
    asm("mov.b64 %0, {%1, %1};" : "=l"(r) : "r"(u));
    return r;
}
__device__ __forceinline__ void ffma2(unsigned long long& d,
                                      unsigned long long a, unsigned long long b) {
    asm("fma.rn.f32x2 %0, %1, %2, %0;" : "+l"(d) : "l"(a), "l"(b));
}
__device__ __forceinline__ void unpack2(unsigned long long v, float& lo, float& hi) {
    asm("mov.b64 {%0, %1}, %2;" : "=f"(lo), "=f"(hi) : "l"(v));
}

// ---------------- 128-bit vector reduction (sm_90+) ------------------------
__device__ __forceinline__ void red4(float* p, float a, float b, float c, float d) {
    asm volatile("red.global.add.v4.f32 [%0], {%1,%2,%3,%4};"
                 :: "l"(p), "f"(a), "f"(b), "f"(c), "f"(d) : "memory");
}

// ---------------- detect int64 vs int32 edge_index -------------------------
__global__ void detect_kernel(const unsigned int* __restrict__ w) {
    unsigned v = w[threadIdx.x * 2 + 1];
    int any = __syncthreads_or(v != 0u);
    if (threadIdx.x == 0) g_is64 = any ? 0 : 1;
}

// ---------------- zero one agg buffer ---------------------------------------
__global__ void zero_buf(float* buf) {
    int i = blockIdx.x * blockDim.x + threadIdx.x;
    if (i < NN * 2) ((float4*)buf)[i] = make_float4(0.f, 0.f, 0.f, 0.f);
}

// ---------------- layer-1: g_tmp = x @ W1 (512 -> 8) -----------------------
// 8-lane groups, 4 nodes/group. W1 in shared (transposed f32-pairs, XOR
// swizzle). p-loop split in halves to keep W-regs at 16; x bcast transient.
__global__ void __launch_bounds__(256, 3) l1_kernel(const float* __restrict__ x,
                                                    const float* __restrict__ W1) {
    __shared__ __align__(16) unsigned long long sh2[2048];   // 16 KB
    const int tid = threadIdx.x;

    // stage: byte addr = i*1024 + r*128 + ((p*2+which) ^ r)*16
    // holds pairs {W1[k][2p],W1[k][2p+1]}, k = i*32 + r*4 + which*2 (+1)
#pragma unroll
    for (int s = tid; s < 1024; s += 256) {
        int i  = s >> 6;
        int r  = (s >> 3) & 7;
        int gp = s & 7;
        int pw = gp ^ r;
        int p = pw >> 1, which = pw & 1;
        int k0 = i * 32 + r * 4 + which * 2;
        unsigned a0 = __float_as_uint(__ldg(&W1[k0 * 8 + 2 * p]));
        unsigned a1 = __float_as_uint(__ldg(&W1[k0 * 8 + 2 * p + 1]));
        unsigned b0 = __float_as_uint(__ldg(&W1[(k0 + 1) * 8 + 2 * p]));
        unsigned b1 = __float_as_uint(__ldg(&W1[(k0 + 1) * 8 + 2 * p + 1]));
        unsigned long long lo, hi;
        asm("mov.b64 %0, {%1, %2};" : "=l"(lo) : "r"(a0), "r"(a1));
        asm("mov.b64 %0, {%1, %2};" : "=l"(hi) : "r"(b0), "r"(b1));
        *(ulonglong2*)((char*)sh2 + s * 16) = make_ulonglong2(lo, hi);
    }
    __syncthreads();

    const int lane = tid & 31;
    const int warp = tid >> 5;
    const int g = lane >> 3;
    const int r = lane & 7;

    const int nbase = blockIdx.x * 128 + warp * 16 + g * 4;
    const float* xr0 = x + (size_t)min(nbase + 0, NN - 1) * 512;
    const float* xr1 = x + (size_t)min(nbase + 1, NN - 1) * 512;
    const float* xr2 = x + (size_t)min(nbase + 2, NN - 1) * 512;
    const float* xr3 = x + (size_t)min(nbase + 3, NN - 1) * 512;

    const char* shb = (const char*)sh2 + r * 128;

    unsigned long long acc[4][4];   // [node][p]
#pragma unroll
    for (int j = 0; j < 4; j++)
#pragma unroll
        for (int p = 0; p < 4; p++) acc[j][p] = 0ull;

#pragma unroll 2
    for (int i = 0; i < 16; i++) {
        int kbase = i * 32 + r * 4;
        float4 v[4];
        v[0] = __ldg((const float4*)(xr0 + kbase));
        v[1] = __ldg((const float4*)(xr1 + kbase));
        v[2] = __ldg((const float4*)(xr2 + kbase));
        v[3] = __ldg((const float4*)(xr3 + kbase));

        const char* row = shb + i * 1024;
#pragma unroll
        for (int half = 0; half < 2; half++) {
            // W regs for p = 2*half, 2*half+1 only (16 regs live)
            ulonglong2 wA0 = *(const ulonglong2*)(row + ((((2 * half + 0) * 2 + 0) ^ r) << 4));
            ulonglong2 wB0 = *(const ulonglong2*)(row + ((((2 * half + 0) * 2 + 1) ^ r) << 4));
            ulonglong2 wA1 = *(const ulonglong2*)(row + ((((2 * half + 1) * 2 + 0) ^ r) << 4));
            ulonglong2 wB1 = *(const ulonglong2*)(row + ((((2 * half + 1) * 2 + 1) ^ r) << 4));
#pragma unroll
            for (int j = 0; j < 4; j++) {
                unsigned long long xb;
                xb = bcast2(v[j].x);
                ffma2(acc[j][2 * half + 0], xb, wA0.x);
                ffma2(acc[j][2 * half + 1], xb, wA1.x);
                xb = bcast2(v[j].y);
                ffma2(acc[j][2 * half + 0], xb, wA0.y);
                ffma2(acc[j][2 * half + 1], xb, wA1.y);
                xb = bcast2(v[j].z);
                ffma2(acc[j][2 * half + 0], xb, wB0.x);
                ffma2(acc[j][2 * half + 1], xb, wB1.x);
                xb = bcast2(v[j].w);
                ffma2(acc[j][2 * half + 0], xb, wB0.y);
                ffma2(acc[j][2 * half + 1], xb, wB1.y);
            }
        }
    }

#pragma unroll
    for (int j = 0; j < 4; j++) {
        float s[8];
#pragma unroll
        for (int p = 0; p < 4; p++) unpack2(acc[j][p], s[2 * p], s[2 * p + 1]);
#pragma unroll
        for (int d = 1; d < 8; d <<= 1) {
#pragma unroll
            for (int o = 0; o < 8; o++)
                s[o] += __shfl_xor_sync(0xffffffffu, s[o], d);
        }
        int node = nbase + j;
        if (r == 0 && node < NN) {
            float4* tp = (float4*)(g_tmp + (size_t)node * 8);
            tp[0] = make_float4(s[0], s[1], s[2], s[3]);
            tp[1] = make_float4(s[4], s[5], s[6], s[7]);
        }
    }
}

// ---------------- edge pass 1: fused convert + scatter (tmp -> aggA) -------
__global__ void edgecv_k(const void* __restrict__ edge_index,
                         const float* __restrict__ w) {
    int e = blockIdx.x * blockDim.x + threadIdx.x;
    if (e >= NE) return;
    int s, d;
    if (g_is64) {
        const long long* p = (const long long*)edge_index;
        s = (int)__ldg(&p[e]); d = (int)__ldg(&p[NE + e]);
    } else {
        const int* p = (const int*)edge_index;
        s = __ldg(&p[e]); d = __ldg(&p[NE + e]);
    }
    g_edge[e] = make_int2(s, d);
    float wt = __ldg(&w[e]);
    const float4* ts = (const float4*)(g_tmp + (size_t)s * 8);
    float* ad = g_aggA + (size_t)d * 8;
    float4 a = __ldg(ts);
    float4 b = __ldg(ts + 1);
    red4(ad,     a.x * wt, a.y * wt, a.z * wt, a.w * wt);
    red4(ad + 4, b.x * wt, b.y * wt, b.z * wt, b.w * wt);
}

// ---------------- edge pass: plain (tmp -> aggA) ---------------------------
__global__ void edge_k(const float* __restrict__ w) {
    int e = blockIdx.x * blockDim.x + threadIdx.x;
    if (e >= NE) return;
    int2 sd = __ldg(&g_edge[e]);
    float wt = __ldg(&w[e]);
    const float4* ts = (const float4*)(g_tmp + (size_t)sd.x * 8);
    float* ad = g_aggA + (size_t)sd.y * 8;
    float4 a = __ldg(ts);
    float4 b = __ldg(ts + 1);
    red4(ad,     a.x * wt, a.y * wt, a.z * wt, a.w * wt);
    red4(ad + 4, b.x * wt, b.y * wt, b.z * wt, b.w * wt);
}

// ---------------- edge pass with fused relu: relu(aggA[src]+b)*w -> aggB ---
__global__ void edge_relu_k(const float* __restrict__ w,
                            const float* __restrict__ bias) {
    int e = blockIdx.x * blockDim.x + threadIdx.x;
    if (e >= NE) return;
    int2 sd = __ldg(&g_edge[e]);
    float wt = __ldg(&w[e]);
    const float4* ts = (const float4*)(g_aggA + (size_t)sd.x * 8);
    float* ad = g_aggB + (size_t)sd.y * 8;
    float4 a = __ldg(ts);
    float4 b = __ldg(ts + 1);
    float h0 = fmaxf(a.x + __ldg(&bias[0]), 0.f);
    float h1 = fmaxf(a.y + __ldg(&bias[1]), 0.f);
    float h2 = fmaxf(a.z + __ldg(&bias[2]), 0.f);
    float h3 = fmaxf(a.w + __ldg(&bias[3]), 0.f);
    float h4 = fmaxf(b.x + __ldg(&bias[4]), 0.f);
    float h5 = fmaxf(b.y + __ldg(&bias[5]), 0.f);
    float h6 = fmaxf(b.z + __ldg(&bias[6]), 0.f);
    float h7 = fmaxf(b.w + __ldg(&bias[7]), 0.f);
    red4(ad,     h0 * wt, h1 * wt, h2 * wt, h3 * wt);
    red4(ad + 4, h4 * wt, h5 * wt, h6 * wt, h7 * wt);
}

// ---------------- fused mid: tmp = relu(aggB@W2 + b2) @ W3; zero aggA,aggB -
__global__ void tmid(const float* __restrict__ W2, const float* __restrict__ b2,
                     const float* __restrict__ W3) {
    int n = blockIdx.x * blockDim.x + threadIdx.x;
    if (n >= NN) return;
    float4* brow = (float4*)(g_aggB + (size_t)n * 8);
    float4 v0 = brow[0], v1 = brow[1];
    float h[8] = {v0.x, v0.y, v0.z, v0.w, v1.x, v1.y, v1.z, v1.w};
    float4 z = make_float4(0.f, 0.f, 0.f, 0.f);
    brow[0] = z; brow[1] = z;
    float4* arow = (float4*)(g_aggA + (size_t)n * 8);
    arow[0] = z; arow[1] = z;

    float m[16];
#pragma unroll
    for (int o = 0; o < 16; o++) m[o] = __ldg(&b2[o]);
#pragma unroll
    for (int j = 0; j < 8; j++) {
        float hj = h[j];
#pragma unroll
        for (int o = 0; o < 16; o++)
            m[o] += hj * __ldg(&W2[j * 16 + o]);
    }
#pragma unroll
    for (int o = 0; o < 16; o++) m[o] = fmaxf(m[o], 0.f);

    float acc[8];
#pragma unroll
    for (int o = 0; o < 8; o++) acc[o] = 0.f;
#pragma unroll
    for (int j = 0; j < 16; j++) {
        float mj = m[j];
#pragma unroll
        for (int o = 0; o < 8; o++)
            acc[o] += mj * __ldg(&W3[j * 8 + o]);
    }
    float4* trow = (float4*)(g_tmp + (size_t)n * 8);
    trow[0] = make_float4(acc[0], acc[1], acc[2], acc[3]);
    trow[1] = make_float4(acc[4], acc[5], acc[6], acc[7]);
}

// ---------------- final: out = log_softmax(aggB@W4 + b4) -------------------
__global__ void lsm_kernel(const float* __restrict__ W4, const float* __restrict__ b4,
                           float* __restrict__ out) {
    int n = blockIdx.x * blockDim.x + threadIdx.x;
    if (n >= NN) return;
    const float4* brow = (const float4*)(g_aggB + (size_t)n * 8);
    float4 v0 = __ldg(brow), v1 = __ldg(brow + 1);
    float h[8] = {v0.x, v0.y, v0.z, v0.w, v1.x, v1.y, v1.z, v1.w};

    float v[10];
#pragma unroll
    for (int o = 0; o < 10; o++) v[o] = __ldg(&b4[o]);
#pragma unroll
    for (int j = 0; j < 8; j++) {
        float hj = h[j];
#pragma unroll
        for (int o = 0; o < 10; o++)
            v[o] += hj * __ldg(&W4[j * 10 + o]);
    }
    float m = -1e30f;
#pragma unroll
    for (int o = 0; o < 10; o++) m = fmaxf(m, v[o]);
    float s = 0.f;
#pragma unroll
    for (int o = 0; o < 10; o++) s += expf(v[o] - m);
    float l = logf(s);
#pragma unroll
    for (int o = 0; o < 10; o++) out[(size_t)n * 10 + o] = v[o] - m - l;
}

// ---------------- launch ---------------------------------------------------
extern "C" void kernel_launch(void* const* d_in, const int* in_sizes, int n_in,
                              void* d_out, int out_size) {
    const float* x  = (const float*)d_in[0];
    const void*  ei = d_in[1];
    const float* ew = (const float*)d_in[2];
    const float* W1 = (const float*)d_in[3];
    const float* b1 = (const float*)d_in[4];
    const float* W2 = (const float*)d_in[5];
    const float* b2 = (const float*)d_in[6];
    const float* W3 = (const float*)d_in[7];
    const float* b3 = (const float*)d_in[8];
    const float* W4 = (const float*)d_in[9];
    const float* b4 = (const float*)d_in[10];
    float* out = (float*)d_out;

    float* aggA; cudaGetSymbolAddress((void**)&aggA, g_aggA);
    float* aggB; cudaGetSymbolAddress((void**)&aggB, g_aggB);

    const int ZBLK = (NN * 2 + 255) / 256;
    detect_kernel<<<1, 256>>>((const unsigned int*)ei);      // 0
    zero_buf<<<ZBLK, 256>>>(aggA);                           // 1
    zero_buf<<<ZBLK, 256>>>(aggB);                           // 2
    l1_kernel<<<(NN + 127) / 128, 256>>>(x, W1);             // 3 (profiled)
    edgecv_k<<<EBLK, 256>>>(ei, ew);                         // 4: aggA = A@(xW1)

    edge_relu_k<<<EBLK, 256>>>(ew, b1);                      // aggB = A@relu(aggA+b1)
    tmid<<<NBLK, 256>>>(W2, b2, W3);                         // tmp = relu(aggB W2+b2)W3; aggA=aggB=0
    edge_k<<<EBLK, 256>>>(ew);                               // aggA = A@tmp
    edge_relu_k<<<EBLK, 256>>>(ew, b3);                      // aggB = A@relu(aggA+b3)
    lsm_kernel<<<NBLK, 256>>>(W4, b4, out);                  // out = lsm(aggB W4+b4)
}

// round 12
// speedup vs baseline: 1.2732x; 1.0052x over previous
#include <cuda_runtime.h>
#include <math.h>

#define NN 100000
#define NE 3200000
#define EBLK ((NE + 255) / 256)
#define NBLK ((NN + 255) / 256)

// ---------------- scratch ---------------------------------------------------
__device__ float g_tmp[NN * 8];
__device__ float g_aggA[NN * 8];
__device__ float g_aggB[NN * 8];
__device__ int2  g_edge[NE];
__device__ int   g_is64;

// ---------------- f32x2 helpers --------------------------------------------
__device__ __forceinline__ unsigned long long bcast2(float x) {
    unsigned long long r;
    unsigned u = __float_as_uint(x);
    asm("mov.b64 %0, {%1, %1};" : "=l"(r) : "r"(u));
    return r;
}
__device__ __forceinline__ void ffma2(unsigned long long& d,
                                      unsigned long long a, unsigned long long b) {
    asm("fma.rn.f32x2 %0, %1, %2, %0;" : "+l"(d) : "l"(a), "l"(b));
}
__device__ __forceinline__ void unpack2(unsigned long long v, float& lo, float& hi) {
    asm("mov.b64 {%0, %1}, %2;" : "=f"(lo), "=f"(hi) : "l"(v));
}

// ---------------- 128-bit vector reduction (sm_90+) ------------------------
__device__ __forceinline__ void red4(float* p, float a, float b, float c, float d) {
    asm volatile("red.global.add.v4.f32 [%0], {%1,%2,%3,%4};"
                 :: "l"(p), "f"(a), "f"(b), "f"(c), "f"(d) : "memory");
}

// ---------------- detect int64 vs int32 edge_index -------------------------
__global__ void detect_kernel(const unsigned int* __restrict__ w) {
    unsigned v = w[threadIdx.x * 2 + 1];
    int any = __syncthreads_or(v != 0u);
    if (threadIdx.x == 0) g_is64 = any ? 0 : 1;
}

// ---------------- zero one agg buffer ---------------------------------------
__global__ void zero_buf(float* buf) {
    int i = blockIdx.x * blockDim.x + threadIdx.x;
    if (i < NN * 2) ((float4*)buf)[i] = make_float4(0.f, 0.f, 0.f, 0.f);
}

// ---------------- layer-1: g_tmp = x @ W1 (512 -> 8) -----------------------
// 8-lane groups, 4 nodes/group. W1 in shared (transposed f32-pairs, XOR
// swizzle). p-loop split in halves to keep W-regs at 16; x bcast transient.
__global__ void __launch_bounds__(256, 3) l1_kernel(const float* __restrict__ x,
                                                    const float* __restrict__ W1) {
    __shared__ __align__(16) unsigned long long sh2[2048];   // 16 KB
    const int tid = threadIdx.x;

    // stage: byte addr = i*1024 + r*128 + ((p*2+which) ^ r)*16
    // holds pairs {W1[k][2p],W1[k][2p+1]}, k = i*32 + r*4 + which*2 (+1)
#pragma unroll
    for (int s = tid; s < 1024; s += 256) {
        int i  = s >> 6;
        int r  = (s >> 3) & 7;
        int gp = s & 7;
        int pw = gp ^ r;
        int p = pw >> 1, which = pw & 1;
        int k0 = i * 32 + r * 4 + which * 2;
        unsigned a0 = __float_as_uint(__ldg(&W1[k0 * 8 + 2 * p]));
        unsigned a1 = __float_as_uint(__ldg(&W1[k0 * 8 + 2 * p + 1]));
        unsigned b0 = __float_as_uint(__ldg(&W1[(k0 + 1) * 8 + 2 * p]));
        unsigned b1 = __float_as_uint(__ldg(&W1[(k0 + 1) * 8 + 2 * p + 1]));
        unsigned long long lo, hi;
        asm("mov.b64 %0, {%1, %2};" : "=l"(lo) : "r"(a0), "r"(a1));
        asm("mov.b64 %0, {%1, %2};" : "=l"(hi) : "r"(b0), "r"(b1));
        *(ulonglong2*)((char*)sh2 + s * 16) = make_ulonglong2(lo, hi);
    }
    __syncthreads();

    const int lane = tid & 31;
    const int warp = tid >> 5;
    const int g = lane >> 3;
    const int r = lane & 7;

    const int nbase = blockIdx.x * 128 + warp * 16 + g * 4;
    const float* xr0 = x + (size_t)min(nbase + 0, NN - 1) * 512;
    const float* xr1 = x + (size_t)min(nbase + 1, NN - 1) * 512;
    const float* xr2 = x + (size_t)min(nbase + 2, NN - 1) * 512;
    const float* xr3 = x + (size_t)min(nbase + 3, NN - 1) * 512;

    const char* shb = (const char*)sh2 + r * 128;

    unsigned long long acc[4][4];   // [node][p]
#pragma unroll
    for (int j = 0; j < 4; j++)
#pragma unroll
        for (int p = 0; p < 4; p++) acc[j][p] = 0ull;

#pragma unroll 2
    for (int i = 0; i < 16; i++) {
        int kbase = i * 32 + r * 4;
        float4 v[4];
        v[0] = __ldg((const float4*)(xr0 + kbase));
        v[1] = __ldg((const float4*)(xr1 + kbase));
        v[2] = __ldg((const float4*)(xr2 + kbase));
        v[3] = __ldg((const float4*)(xr3 + kbase));

        const char* row = shb + i * 1024;
#pragma unroll
        for (int half = 0; half < 2; half++) {
            // W regs for p = 2*half, 2*half+1 only (16 regs live)
            ulonglong2 wA0 = *(const ulonglong2*)(row + ((((2 * half + 0) * 2 + 0) ^ r) << 4));
            ulonglong2 wB0 = *(const ulonglong2*)(row + ((((2 * half + 0) * 2 + 1) ^ r) << 4));
            ulonglong2 wA1 = *(const ulonglong2*)(row + ((((2 * half + 1) * 2 + 0) ^ r) << 4));
            ulonglong2 wB1 = *(const ulonglong2*)(row + ((((2 * half + 1) * 2 + 1) ^ r) << 4));
#pragma unroll
            for (int j = 0; j < 4; j++) {
                unsigned long long xb;
                xb = bcast2(v[j].x);
                ffma2(acc[j][2 * half + 0], xb, wA0.x);
                ffma2(acc[j][2 * half + 1], xb, wA1.x);
                xb = bcast2(v[j].y);
                ffma2(acc[j][2 * half + 0], xb, wA0.y);
                ffma2(acc[j][2 * half + 1], xb, wA1.y);
                xb = bcast2(v[j].z);
                ffma2(acc[j][2 * half + 0], xb, wB0.x);
                ffma2(acc[j][2 * half + 1], xb, wB1.x);
                xb = bcast2(v[j].w);
                ffma2(acc[j][2 * half + 0], xb, wB0.y);
                ffma2(acc[j][2 * half + 1], xb, wB1.y);
            }
        }
    }

#pragma unroll
    for (int j = 0; j < 4; j++) {
        float s[8];
#pragma unroll
        for (int p = 0; p < 4; p++) unpack2(acc[j][p], s[2 * p], s[2 * p + 1]);
#pragma unroll
        for (int d = 1; d < 8; d <<= 1) {
#pragma unroll
            for (int o = 0; o < 8; o++)
                s[o] += __shfl_xor_sync(0xffffffffu, s[o], d);
        }
        int node = nbase + j;
        if (r == 0 && node < NN) {
            float4* tp = (float4*)(g_tmp + (size_t)node * 8);
            tp[0] = make_float4(s[0], s[1], s[2], s[3]);
            tp[1] = make_float4(s[4], s[5], s[6], s[7]);
        }
    }
}

// ---------------- edge pass 1: fused convert + scatter (tmp -> aggA) -------
__global__ void edgecv_k(const void* __restrict__ edge_index,
                         const float* __restrict__ w) {
    int e = blockIdx.x * blockDim.x + threadIdx.x;
    if (e >= NE) return;
    int s, d;
    if (g_is64) {
        const long long* p = (const long long*)edge_index;
        s = (int)__ldg(&p[e]); d = (int)__ldg(&p[NE + e]);
    } else {
        const int* p = (const int*)edge_index;
        s = __ldg(&p[e]); d = __ldg(&p[NE + e]);
    }
    g_edge[e] = make_int2(s, d);
    float wt = __ldg(&w[e]);
    const float4* ts = (const float4*)(g_tmp + (size_t)s * 8);
    float* ad = g_aggA + (size_t)d * 8;
    float4 a = __ldg(ts);
    float4 b = __ldg(ts + 1);
    red4(ad,     a.x * wt, a.y * wt, a.z * wt, a.w * wt);
    red4(ad + 4, b.x * wt, b.y * wt, b.z * wt, b.w * wt);
}

// ---------------- edge pass: plain (tmp -> aggA) ---------------------------
__global__ void edge_k(const float* __restrict__ w) {
    int e = blockIdx.x * blockDim.x + threadIdx.x;
    if (e >= NE) return;
    int2 sd = __ldg(&g_edge[e]);
    float wt = __ldg(&w[e]);
    const float4* ts = (const float4*)(g_tmp + (size_t)sd.x * 8);
    float* ad = g_aggA + (size_t)sd.y * 8;
    float4 a = __ldg(ts);
    float4 b = __ldg(ts + 1);
    red4(ad,     a.x * wt, a.y * wt, a.z * wt, a.w * wt);
    red4(ad + 4, b.x * wt, b.y * wt, b.z * wt, b.w * wt);
}

// ---------------- edge pass with fused relu: relu(aggA[src]+b)*w -> aggB ---
__global__ void edge_relu_k(const float* __restrict__ w,
                            const float* __restrict__ bias) {
    int e = blockIdx.x * blockDim.x + threadIdx.x;
    if (e >= NE) return;
    int2 sd = __ldg(&g_edge[e]);
    float wt = __ldg(&w[e]);
    const float4* ts = (const float4*)(g_aggA + (size_t)sd.x * 8);
    float* ad = g_aggB + (size_t)sd.y * 8;
    float4 a = __ldg(ts);
    float4 b = __ldg(ts + 1);
    float h0 = fmaxf(a.x + __ldg(&bias[0]), 0.f);
    float h1 = fmaxf(a.y + __ldg(&bias[1]), 0.f);
    float h2 = fmaxf(a.z + __ldg(&bias[2]), 0.f);
    float h3 = fmaxf(a.w + __ldg(&bias[3]), 0.f);
    float h4 = fmaxf(b.x + __ldg(&bias[4]), 0.f);
    float h5 = fmaxf(b.y + __ldg(&bias[5]), 0.f);
    float h6 = fmaxf(b.z + __ldg(&bias[6]), 0.f);
    float h7 = fmaxf(b.w + __ldg(&bias[7]), 0.f);
    red4(ad,     h0 * wt, h1 * wt, h2 * wt, h3 * wt);
    red4(ad + 4, h4 * wt, h5 * wt, h6 * wt, h7 * wt);
}

// ---------------- fused mid: tmp = relu(aggB@W2 + b2) @ W3; zero aggA,aggB -
__global__ void tmid(const float* __restrict__ W2, const float* __restrict__ b2,
                     const float* __restrict__ W3) {
    int n = blockIdx.x * blockDim.x + threadIdx.x;
    if (n >= NN) return;
    float4* brow = (float4*)(g_aggB + (size_t)n * 8);
    float4 v0 = brow[0], v1 = brow[1];
    float h[8] = {v0.x, v0.y, v0.z, v0.w, v1.x, v1.y, v1.z, v1.w};
    float4 z = make_float4(0.f, 0.f, 0.f, 0.f);
    brow[0] = z; brow[1] = z;
    float4* arow = (float4*)(g_aggA + (size_t)n * 8);
    arow[0] = z; arow[1] = z;

    float m[16];
#pragma unroll
    for (int o = 0; o < 16; o++) m[o] = __ldg(&b2[o]);
#pragma unroll
    for (int j = 0; j < 8; j++) {
        float hj = h[j];
#pragma unroll
        for (int o = 0; o < 16; o++)
            m[o] += hj * __ldg(&W2[j * 16 + o]);
    }
#pragma unroll
    for (int o = 0; o < 16; o++) m[o] = fmaxf(m[o], 0.f);

    float acc[8];
#pragma unroll
    for (int o = 0; o < 8; o++) acc[o] = 0.f;
#pragma unroll
    for (int j = 0; j < 16; j++) {
        float mj = m[j];
#pragma unroll
        for (int o = 0; o < 8; o++)
            acc[o] += mj * __ldg(&W3[j * 8 + o]);
    }
    float4* trow = (float4*)(g_tmp + (size_t)n * 8);
    trow[0] = make_float4(acc[0], acc[1], acc[2], acc[3]);
    trow[1] = make_float4(acc[4], acc[5], acc[6], acc[7]);
}

// ---------------- final: out = log_softmax(aggB@W4 + b4) -------------------
__global__ void lsm_kernel(const float* __restrict__ W4, const float* __restrict__ b4,
                           float* __restrict__ out) {
    int n = blockIdx.x * blockDim.x + threadIdx.x;
    if (n >= NN) return;
    const float4* brow = (const float4*)(g_aggB + (size_t)n * 8);
    float4 v0 = __ldg(brow), v1 = __ldg(brow + 1);
    float h[8] = {v0.x, v0.y, v0.z, v0.w, v1.x, v1.y, v1.z, v1.w};

    float v[10];
#pragma unroll
    for (int o = 0; o < 10; o++) v[o] = __ldg(&b4[o]);
#pragma unroll
    for (int j = 0; j < 8; j++) {
        float hj = h[j];
#pragma unroll
        for (int o = 0; o < 10; o++)
            v[o] += hj * __ldg(&W4[j * 10 + o]);
    }
    float m = -1e30f;
#pragma unroll
    for (int o = 0; o < 10; o++) m = fmaxf(m, v[o]);
    float s = 0.f;
#pragma unroll
    for (int o = 0; o < 10; o++) s += expf(v[o] - m);
    float l = logf(s);
#pragma unroll
    for (int o = 0; o < 10; o++) out[(size_t)n * 10 + o] = v[o] - m - l;
}

// ---------------- launch ---------------------------------------------------
extern "C" void kernel_launch(void* const* d_in, const int* in_sizes, int n_in,
                              void* d_out, int out_size) {
    const float* x  = (const float*)d_in[0];
    const void*  ei = d_in[1];
    const float* ew = (const float*)d_in[2];
    const float* W1 = (const float*)d_in[3];
    const float* b1 = (const float*)d_in[4];
    const float* W2 = (const float*)d_in[5];
    const float* b2 = (const float*)d_in[6];
    const float* W3 = (const float*)d_in[7];
    const float* b3 = (const float*)d_in[8];
    const float* W4 = (const float*)d_in[9];
    const float* b4 = (const float*)d_in[10];
    float* out = (float*)d_out;

    float* aggA; cudaGetSymbolAddress((void**)&aggA, g_aggA);
    float* aggB; cudaGetSymbolAddress((void**)&aggB, g_aggB);

    const int ZBLK = (NN * 2 + 255) / 256;
    detect_kernel<<<1, 256>>>((const unsigned int*)ei);      // 0
    zero_buf<<<ZBLK, 256>>>(aggA);                           // 1
    zero_buf<<<ZBLK, 256>>>(aggB);                           // 2
    l1_kernel<<<(NN + 127) / 128, 256>>>(x, W1);             // 3 (profiled)
    edgecv_k<<<EBLK, 256>>>(ei, ew);                         // 4: aggA = A@(xW1)

    edge_relu_k<<<EBLK, 256>>>(ew, b1);                      // aggB = A@relu(aggA+b1)
    tmid<<<NBLK, 256>>>(W2, b2, W3);                         // tmp = relu(aggB W2+b2)W3; aggA=aggB=0
    edge_k<<<EBLK, 256>>>(ew);                               // aggA = A@tmp
    edge_relu_k<<<EBLK, 256>>>(ew, b3);                      // aggB = A@relu(aggA+b3)
    lsm_kernel<<<NBLK, 256>>>(W4, b4, out);                  // out = lsm(aggB W4+b4)
}